// round 7
// baseline (speedup 1.0000x reference)
#include <cuda_runtime.h>
#include <cstdint>
#include <cstddef>

typedef unsigned int u32;
typedef unsigned long long u64;

// ---------------- problem dims ----------------
#define B_DIM 4096
#define I_DIM 256
#define H_DIM 1024
#define O_DIM 4096   // 4*H
#define MPL   4      // bit planes

// ---------------- static device scratch (no allocations allowed) ----------------
// Weff stored plane-major [MPL][K][O], values PRE-HALVED (x0.5, exact):
// inner loop uses FFMA acc, wh, 2.0, acc  (imm-multiplier form, rt_SMSP=1).
__device__ float   g_weff_ih[(size_t)MPL * I_DIM * O_DIM];      // 16 MB
__device__ float   g_weff_hh[(size_t)MPL * H_DIM * O_DIM];      // 64 MB
__device__ float   g_bq_ih[MPL * O_DIM];
__device__ float   g_nb_ih[MPL * O_DIM];
__device__ float   g_bq_hh[MPL * O_DIM];
__device__ float   g_nb_hh[MPL * O_DIM];
__device__ uint8_t g_nib_in[(size_t)B_DIM * I_DIM];             // 1 MB
__device__ uint8_t g_nib_hx[(size_t)B_DIM * H_DIM];             // 4 MB
__device__ float   g_gates1[(size_t)B_DIM * O_DIM];             // 64 MB (part1, ih)
__device__ float   g_gates2[(size_t)B_DIM * O_DIM];             // 64 MB (part2, hh)
__device__ unsigned g_max[4];
__device__ unsigned g_tile;                                      // persistent scheduler

// ---------------- threefry2x32 (JAX-exact) ----------------
__host__ __device__ __forceinline__ void threefry2x32(u32 k0, u32 k1, u32 x0, u32 x1,
                                                      u32 &o0, u32 &o1) {
  u32 ks2 = k0 ^ k1 ^ 0x1BD11BDAu;
  x0 += k0; x1 += k1;
#define TF_ROT(r) { x0 += x1; x1 = (x1 << (r)) | (x1 >> (32 - (r))); x1 ^= x0; }
  TF_ROT(13) TF_ROT(15) TF_ROT(26) TF_ROT(6)   x0 += k1;  x1 += ks2 + 1u;
  TF_ROT(17) TF_ROT(29) TF_ROT(16) TF_ROT(24)  x0 += ks2; x1 += k0 + 2u;
  TF_ROT(13) TF_ROT(15) TF_ROT(26) TF_ROT(6)   x0 += k0;  x1 += k1 + 3u;
  TF_ROT(17) TF_ROT(29) TF_ROT(16) TF_ROT(24)  x0 += k1;  x1 += ks2 + 4u;
  TF_ROT(13) TF_ROT(15) TF_ROT(26) TF_ROT(6)   x0 += ks2; x1 += k0 + 5u;
#undef TF_ROT
  o0 = x0; o1 = x1;
}

// ---------------- XLA-exact f32 transcendentals (unfused rn mul/add) --------
__device__ __forceinline__ float xla_log1p(float x) {
  float u = __fadd_rn(x, 1.0f);
  if (u == 1.0f) return x;
  return __fmul_rn(__fdiv_rn(x, __fsub_rn(u, 1.0f)), logf(u));
}

__device__ __forceinline__ float xla_erfinv(float x) {
  float w = -xla_log1p(__fmul_rn(__fmul_rn(-1.0f, x), x));
  float p;
  if (w < 5.0f) {
    w = __fsub_rn(w, 2.5f);
    p = 2.81022636e-08f;
    p = __fadd_rn(__fmul_rn(p, w), 3.43273939e-07f);
    p = __fadd_rn(__fmul_rn(p, w), -3.5233877e-06f);
    p = __fadd_rn(__fmul_rn(p, w), -4.39150654e-06f);
    p = __fadd_rn(__fmul_rn(p, w), 0.00021858087f);
    p = __fadd_rn(__fmul_rn(p, w), -0.00125372503f);
    p = __fadd_rn(__fmul_rn(p, w), -0.00417768164f);
    p = __fadd_rn(__fmul_rn(p, w), 0.246640727f);
    p = __fadd_rn(__fmul_rn(p, w), 1.50140941f);
  } else {
    w = __fsub_rn(sqrtf(w), 3.0f);
    p = -0.000200214257f;
    p = __fadd_rn(__fmul_rn(p, w), 0.000100950558f);
    p = __fadd_rn(__fmul_rn(p, w), 0.00134934322f);
    p = __fadd_rn(__fmul_rn(p, w), -0.00367342844f);
    p = __fadd_rn(__fmul_rn(p, w), 0.00573950773f);
    p = __fadd_rn(__fmul_rn(p, w), -0.0076224613f);
    p = __fadd_rn(__fmul_rn(p, w), 0.00943887047f);
    p = __fadd_rn(__fmul_rn(p, w), 1.00167406f);
    p = __fadd_rn(__fmul_rn(p, w), 2.83297682f);
  }
  return __fmul_rn(p, x);
}

__device__ __forceinline__ float xla_tanh(float x) {
  float ax = fabsf(x);
  if (ax < 0.0004f) return x;
  float xc = fminf(fmaxf(x, -7.90531110763549805f), 7.90531110763549805f);
  float x2 = __fmul_rn(xc, xc);
  float p = -2.76076847742355e-16f;
  p = __fadd_rn(__fmul_rn(p, x2), 2.00018790482477e-13f);
  p = __fadd_rn(__fmul_rn(p, x2), -8.60467152213735e-11f);
  p = __fadd_rn(__fmul_rn(p, x2), 5.12229709037114e-08f);
  p = __fadd_rn(__fmul_rn(p, x2), 1.48572235717979e-05f);
  p = __fadd_rn(__fmul_rn(p, x2), 6.37261928875436e-04f);
  p = __fadd_rn(__fmul_rn(p, x2), 4.89352455891786e-03f);
  p = __fmul_rn(p, xc);
  float q = 1.19825839466702e-06f;
  q = __fadd_rn(__fmul_rn(q, x2), 1.18534705686654e-04f);
  q = __fadd_rn(__fmul_rn(q, x2), 2.26843463243900e-03f);
  q = __fadd_rn(__fmul_rn(q, x2), 4.89352518554385e-03f);
  return __fdiv_rn(p, q);
}

__device__ __forceinline__ float xla_logistic(float x) {
  return __fadd_rn(0.5f, __fmul_rn(0.5f, xla_tanh(__fmul_rn(0.5f, x))));
}

// bits -> N(0,1) exactly as jax.random.normal (float32 path)
__device__ __forceinline__ float bits_to_normal(u32 bits) {
  float u = __uint_as_float((bits >> 9) | 0x3F800000u) - 1.0f;   // [0,1)
  const float lo = __uint_as_float(0xBF7FFFFFu);                 // nextafter(-1,0)
  float v = __fadd_rn(__fmul_rn(u, 2.0f), lo);
  v = fmaxf(v, lo);
  return __fmul_rn(__uint_as_float(0x3FB504F3u) /*sqrt2*/, xla_erfinv(v));
}

// partitionable threefry random_bits: bits[j] = o0 ^ o1 of TF(key, 0, j)
__device__ __forceinline__ u32 jax_bits32(u32 k0, u32 k1, u32 j) {
  u32 o0, o1; threefry2x32(k0, k1, 0u, j, o0, o1);
  return o0 ^ o1;
}

// ---------------- float max encoding for atomicMax ----------------
__device__ __forceinline__ unsigned fenc(float f) {
  unsigned u = __float_as_uint(f);
  return (u & 0x80000000u) ? ~u : (u | 0x80000000u);
}
__device__ __forceinline__ float fdec(unsigned u) {
  return (u & 0x80000000u) ? __uint_as_float(u & 0x7FFFFFFFu) : __uint_as_float(~u);
}

__global__ void k_init_max() {
  if (threadIdx.x < 4) g_max[threadIdx.x] = fenc(-__int_as_float(0x7F800000));
  if (threadIdx.x == 0) g_tile = 0u;
}

__global__ void k_max(const float* __restrict__ x, int n, int slot) {
  float m = -__int_as_float(0x7F800000);
  for (int i = blockIdx.x * blockDim.x + threadIdx.x; i < n; i += gridDim.x * blockDim.x)
    m = fmaxf(m, x[i]);
#pragma unroll
  for (int o = 16; o; o >>= 1) m = fmaxf(m, __shfl_xor_sync(0xFFFFFFFFu, m, o));
  if ((threadIdx.x & 31) == 0) atomicMax(&g_max[slot], fenc(m));
}

// quant(x, 8, 1.0) for weights
__device__ __forceinline__ float quant_w(float x) {
  float xs = fminf(fmaxf(x, -0.9921875f), 0.9921875f);
  return __fmul_rn(__fdiv_rn(rintf(__fmul_rn(xs, 128.0f)), 128.0f), 1.0f);
}

// Weff_half[j] = 0.5 * (quant(W[j]) + normal(j)*wmax*0.1)  (layout == source layout)
__global__ void k_build_w(const float* __restrict__ W, int n, u32 kk0, u32 kk1,
                          int slot, int which_hh) {
  int j = blockIdx.x * blockDim.x + threadIdx.x;
  if (j >= n) return;
  float* dst = which_hh ? g_weff_hh : g_weff_ih;
  float wmax = fdec(g_max[slot]);
  float nr = bits_to_normal(jax_bits32(kk0, kk1, (u32)j));
  float weff = __fadd_rn(quant_w(W[j]), __fmul_rn(__fmul_rn(nr, wmax), 0.1f));
  dst[j] = __fmul_rn(0.5f, weff);   // exact halving of a normal fp32
}

// biases: bq and nb separate so the (mm + bq) + nb add order matches reference
__global__ void k_build_b(const float* __restrict__ Bsrc, int n, u32 kk0, u32 kk1,
                          int slot, int which_hh) {
  int j = blockIdx.x * blockDim.x + threadIdx.x;
  if (j >= n) return;
  float* bq = which_hh ? g_bq_hh : g_bq_ih;
  float* nb = which_hh ? g_nb_hh : g_nb_ih;
  float bmax = fdec(g_max[slot]);
  bq[j] = quant_w(Bsrc[j]);
  nb[j] = __fmul_rn(__fmul_rn(bits_to_normal(jax_bits32(kk0, kk1, (u32)j)), bmax), 0.1f);
}

// activation -> 4-bit plane nibble
__global__ void k_nib(const float* __restrict__ x, uint8_t* __restrict__ nib, int n,
                      const float* __restrict__ aP, const float* __restrict__ offP) {
  int i = blockIdx.x * blockDim.x + threadIdx.x;
  if (i >= n) return;
  float a = *aP, off = *offP;
  float t = __fdiv_rn(__fadd_rn(fminf(fmaxf(x[i], -a), a), off), __fmul_rn(a, 2.0f));
  float v = rintf(__fmul_rn(15.0f, t));
  nib[i] = (uint8_t)(((int)v) & 15);
}

// ---------------- persistent GEMM: predicated scalar FFMA-imm (rt1) ----------
// acc = rn(wh*2.0 + acc) when bit set; wh = weff/2 exact -> product == weff
// exactly inside the fused multiply -> rn(weff + acc), bit-identical to the
// reference's sequential ascending-k fp32 chain. Skip == rn(weff*0 + acc).
#define BM 64
#define BN 64
#define KC 32
#define N_TILES_HH 4096
#define N_TILES_ALL 8192
#define GRID_GEMM 296

// 8 guarded FFMA-imm (one predicate, 8 outputs)
#define FMA8(A, W, bit)                                                        \
  asm volatile("{\n\t.reg .pred p;\n\tsetp.ne.u32 p, %16, 0;\n\t"              \
               "@p fma.rn.f32 %0, %8,  0F40000000, %0;\n\t"                    \
               "@p fma.rn.f32 %1, %9,  0F40000000, %1;\n\t"                    \
               "@p fma.rn.f32 %2, %10, 0F40000000, %2;\n\t"                    \
               "@p fma.rn.f32 %3, %11, 0F40000000, %3;\n\t"                    \
               "@p fma.rn.f32 %4, %12, 0F40000000, %4;\n\t"                    \
               "@p fma.rn.f32 %5, %13, 0F40000000, %5;\n\t"                    \
               "@p fma.rn.f32 %6, %14, 0F40000000, %6;\n\t"                    \
               "@p fma.rn.f32 %7, %15, 0F40000000, %7;\n\t}"                   \
               : "+f"((A)[0]), "+f"((A)[1]), "+f"((A)[2]), "+f"((A)[3]),       \
                 "+f"((A)[4]), "+f"((A)[5]), "+f"((A)[6]), "+f"((A)[7])        \
               : "f"((W)[0]), "f"((W)[1]), "f"((W)[2]), "f"((W)[3]),           \
                 "f"((W)[4]), "f"((W)[5]), "f"((W)[6]), "f"((W)[7]),           \
                 "r"(bit))

#define SW_KSTRIDE 68                 // floats per (m,k) smem row (64 + pad)
#define SW_MSTRIDE (KC * SW_KSTRIDE + 4)

__launch_bounds__(256, 2)
__global__ void k_gemm_all(const float* __restrict__ a1P, const float* __restrict__ a11P) {
  __shared__ __align__(16) float sW[MPL * SW_MSTRIDE];  // ~35 KB (reused as bits)
  __shared__ u32 sA[BM][KC / 4];                        // 2 KB
  __shared__ float sPtab[16];
  __shared__ u32 sTile;

  int tid = threadIdx.x;
  int tx = tid & 3;                   // 16-col group
  int m  = (tid >> 2) & 3;            // plane
  int rg = tid >> 4;                  // 4-row group
  int sh_base = 3 - m;                // nibble bit for plane m

  // exact sequential-fadd beta table: p = fadd-chain over m ascending
  if (tid < 16) {
    const float beta[MPL] = {8.0f / 15.0f, 4.0f / 15.0f, 2.0f / 15.0f, 1.0f / 15.0f};
    float p = 0.0f;
#pragma unroll
    for (int mm = 0; mm < MPL; ++mm)
      p = __fadd_rn(p, ((tid >> (3 - mm)) & 1) ? beta[mm] : 0.0f);
    sPtab[tid] = p;
  }

  while (true) {
    if (tid == 0) sTile = atomicAdd(&g_tile, 1u);
    __syncthreads();                 // orders sPtab init / prev-tile smem reuse
    u32 t = sTile;
    if (t >= N_TILES_ALL) break;

    bool hh = (t < N_TILES_HH);
    u32 t2 = hh ? t : (t - N_TILES_HH);
    int K = hh ? H_DIM : I_DIM;
    const float* __restrict__ Wg = hh ? g_weff_hh : g_weff_ih;   // [MPL][K][O], halved
    const float* __restrict__ bq = hh ? g_bq_hh : g_bq_ih;
    const float* __restrict__ nb = hh ? g_nb_hh : g_nb_ih;
    const uint8_t* __restrict__ nibp = hh ? g_nib_hx : g_nib_in;
    float* __restrict__ gout = hh ? g_gates2 : g_gates1;
    float a = hh ? *a11P : *a1P;

    int ob = (int)(t2 & 63) * BN;
    int bb = (int)(t2 >> 6) * BM;

    float acc[4][16];                 // [row][col], this thread's plane m
#pragma unroll
    for (int r = 0; r < 4; ++r)
#pragma unroll
      for (int c = 0; c < 16; ++c) acc[r][c] = 0.0f;

    for (int k0 = 0; k0 < K; k0 += KC) {
#pragma unroll
      for (int tt = 0; tt < 2; ++tt) {            // A tile: 64 rows x 8 u32
        int idx = tid + tt * 256;
        int r = idx >> 3, k4 = idx & 7;
        sA[r][k4] = *(const u32*)(nibp + (size_t)(bb + r) * K + k0 + k4 * 4);
      }
#pragma unroll
      for (int tt = 0; tt < 8; ++tt) {            // W tile: 2048 coalesced float4
        int idx = tid + tt * 256;
        int mm = idx >> 9, k = (idx >> 4) & 31, q = idx & 15;
        *(float4*)&sW[mm * SW_MSTRIDE + k * SW_KSTRIDE + q * 4] =
            *(const float4*)(Wg + ((size_t)mm * K + k0 + k) * O_DIM + ob + q * 4);
      }
      __syncthreads();

      const float* sWm = sW + m * SW_MSTRIDE + tx * 16;
#pragma unroll 1
      for (int k4 = 0; k4 < KC / 4; ++k4) {
        u32 av0 = sA[rg * 4 + 0][k4];
        u32 av1 = sA[rg * 4 + 1][k4];
        u32 av2 = sA[rg * 4 + 2][k4];
        u32 av3 = sA[rg * 4 + 3][k4];
#pragma unroll
        for (int s = 0; s < 4; ++s) {
          int k = k4 * 4 + s;
          float w[16];
          *(float4*)&w[0]  = *(const float4*)&sWm[k * SW_KSTRIDE + 0];
          *(float4*)&w[4]  = *(const float4*)&sWm[k * SW_KSTRIDE + 4];
          *(float4*)&w[8]  = *(const float4*)&sWm[k * SW_KSTRIDE + 8];
          *(float4*)&w[12] = *(const float4*)&sWm[k * SW_KSTRIDE + 12];
          int sh = 8 * s + sh_base;
          u32 b0 = (av0 >> sh) & 1u;
          u32 b1 = (av1 >> sh) & 1u;
          u32 b2 = (av2 >> sh) & 1u;
          u32 b3 = (av3 >> sh) & 1u;
          FMA8(&acc[0][0], &w[0], b0); FMA8(&acc[0][8], &w[8], b0);
          FMA8(&acc[1][0], &w[0], b1); FMA8(&acc[1][8], &w[8], b1);
          FMA8(&acc[2][0], &w[0], b2); FMA8(&acc[2][8], &w[8], b2);
          FMA8(&acc[3][0], &w[0], b3); FMA8(&acc[3][8], &w[8], b3);
        }
      }
      __syncthreads();
    }

    // ---- epilogue phase 1: s = rn(rn(acc+bq)+nb) > 0.5 -> bit bytes in smem
    {
      uint8_t* sBit = (uint8_t*)sW;   // 16 KB region, reused
      float bqv[16], nbv[16];
      int obase = ob + tx * 16;
#pragma unroll
      for (int q = 0; q < 4; ++q) {
        *(float4*)&bqv[q * 4] = *(const float4*)(bq + m * O_DIM + obase + q * 4);
        *(float4*)&nbv[q * 4] = *(const float4*)(nb + m * O_DIM + obase + q * 4);
      }
#pragma unroll
      for (int r = 0; r < 4; ++r) {
        int rIdx = rg * 4 + r;
#pragma unroll
        for (int c = 0; c < 16; ++c) {
          float s = __fadd_rn(__fadd_rn(acc[r][c], bqv[c]), nbv[c]);
          sBit[((rIdx << 6) + tx * 16 + c) * 4 + m] = (s > 0.5f) ? 1u : 0u;
        }
      }
    }
    __syncthreads();

    // ---- epilogue phase 2: nibble -> exact beta-sum table -> part -> store
    {
      const u32* sWord = (const u32*)sW;
      float twoa = __fmul_rn(a, 2.0f);
      int base = tid * 16;
#pragma unroll
      for (int j = 0; j < 16; ++j) {
        int idx = base + j;
        u32 word = sWord[idx];        // bytes: m0,m1,m2,m3 bits
        u32 nib = ((word & 1u) << 3) | (((word >> 8) & 1u) << 2) |
                  (((word >> 16) & 1u) << 1) | ((word >> 24) & 1u);
        float part = __fsub_rn(__fmul_rn(sPtab[nib], twoa), a);
        gout[(size_t)(bb + (idx >> 6)) * O_DIM + ob + (idx & 63)] = part;
      }
    }
    // next loop-top __syncthreads orders phase-2 reads before restaging
  }
}

// ---------------- quantized LSTM pointwise tail ----------------
__device__ __forceinline__ float pactf(float x, float a) { return fminf(fmaxf(x, -a), a); }
__device__ __forceinline__ float quant8(float x, float r) {
  float xs = __fdiv_rn(x, r);
  xs = fminf(fmaxf(xs, -0.9921875f), 0.9921875f);
  return __fmul_rn(__fdiv_rn(rintf(__fmul_rn(xs, 128.0f)), 128.0f), r);
}

__global__ void k_lstm(const float* __restrict__ cx, float* __restrict__ out,
                       const float* a3, const float* a4, const float* a5, const float* a6,
                       const float* a7, const float* a8, const float* a9, const float* a10,
                       const float* a11) {
  int idx = blockIdx.x * blockDim.x + threadIdx.x;
  if (idx >= B_DIM * H_DIM) return;
  int b = idx >> 10, h = idx & (H_DIM - 1);
  const float* g1 = g_gates1 + (size_t)b * O_DIM;
  const float* g2 = g_gates2 + (size_t)b * O_DIM;
  float gi = __fadd_rn(g1[h],        g2[h]);
  float gj = __fadd_rn(g1[h + 1024], g2[h + 1024]);
  float gf = __fadd_rn(g1[h + 2048], g2[h + 2048]);
  float go = __fadd_rn(g1[h + 3072], g2[h + 3072]);

  float v3 = *a3, v4 = *a4, v5 = *a5, v6 = *a6, v7 = *a7, v8 = *a8, v9 = *a9,
        v10 = *a10, v11 = *a11;
  float fg  = quant8(pactf(xla_logistic(gf), v3), v3);
  float ig  = quant8(pactf(xla_logistic(gi), v4), v4);
  float act = quant8(pactf(xla_tanh(gj), v5), v5);
  float og  = quant8(pactf(xla_logistic(go), v6), v6);
  float gated = quant8(pactf(__fmul_rn(cx[idx], fg), v7), v7);
  float actin = quant8(pactf(__fmul_rn(ig, act), v8), v8);
  float newc  = quant8(pactf(__fadd_rn(gated, actin), v9), v9);
  float actc  = quant8(pactf(xla_tanh(newc), v10), v10);
  float newh  = quant8(pactf(__fmul_rn(actc, og), v11), v11);
  out[idx] = newh;
  out[(size_t)B_DIM * H_DIM + idx] = newc;
}

// ---------------- host side ----------------
static void split2(const u32 k[2], u32 ka[2], u32 kb[2]) {
  threefry2x32(k[0], k[1], 0u, 0u, ka[0], ka[1]);
  threefry2x32(k[0], k[1], 0u, 1u, kb[0], kb[1]);
}

extern "C" void kernel_launch(void* const* d_in, const int* in_sizes, int n_in,
                              void* d_out, int out_size) {
  const float* input = (const float*)d_in[0];
  const float* hx    = (const float*)d_in[1];
  const float* cx    = (const float*)d_in[2];
  const float* wih   = (const float*)d_in[3];
  const float* whh   = (const float*)d_in[4];
  const float* bih   = (const float*)d_in[5];
  const float* bhh   = (const float*)d_in[6];
  const float* a1  = (const float*)d_in[7];
  const float* a3  = (const float*)d_in[8];
  const float* a4  = (const float*)d_in[9];
  const float* a5  = (const float*)d_in[10];
  const float* a6  = (const float*)d_in[11];
  const float* a7  = (const float*)d_in[12];
  const float* a8  = (const float*)d_in[13];
  const float* a9  = (const float*)d_in[14];
  const float* a10 = (const float*)d_in[15];
  const float* a11 = (const float*)d_in[16];

  u32 root[2] = {0u, 42u}, K1[2], K2[2], KW1[2], KB1[2], KW2[2], KB2[2];
  split2(root, K1, K2);
  split2(K1, KW1, KB1);
  split2(K2, KW2, KB2);

  const int n_wih = MPL * I_DIM * O_DIM;   // 4,194,304
  const int n_whh = MPL * H_DIM * O_DIM;   // 16,777,216
  const int n_b   = MPL * O_DIM;           // 16,384

  k_init_max<<<1, 32>>>();
  k_max<<<512, 256>>>(wih, n_wih, 0);
  k_max<<<512, 256>>>(whh, n_whh, 1);
  k_max<<<64, 256>>>(bih, n_b, 2);
  k_max<<<64, 256>>>(bhh, n_b, 3);

  k_build_w<<<(n_wih + 255) / 256, 256>>>(wih, n_wih, KW1[0], KW1[1], 0, 0);
  k_build_w<<<(n_whh + 255) / 256, 256>>>(whh, n_whh, KW2[0], KW2[1], 1, 1);
  k_build_b<<<(n_b + 255) / 256, 256>>>(bih, n_b, KB1[0], KB1[1], 2, 0);
  k_build_b<<<(n_b + 255) / 256, 256>>>(bhh, n_b, KB2[0], KB2[1], 3, 1);

  {
    uint8_t* nin; cudaGetSymbolAddress((void**)&nin, g_nib_in);
    uint8_t* nhx; cudaGetSymbolAddress((void**)&nhx, g_nib_hx);
    k_nib<<<(B_DIM * I_DIM + 255) / 256, 256>>>(input, nin, B_DIM * I_DIM, a1, a1);
    k_nib<<<(B_DIM * H_DIM + 255) / 256, 256>>>(hx, nhx, B_DIM * H_DIM, a11, a1);
  }

  // one persistent kernel: hh tiles (0..4095) then ih tiles (4096..8191)
  k_gemm_all<<<GRID_GEMM, 256>>>(a1, a11);

  k_lstm<<<(B_DIM * H_DIM + 255) / 256, 256>>>(cx, (float*)d_out,
                                               a3, a4, a5, a6, a7, a8, a9, a10, a11);
}

// round 8
// speedup vs baseline: 1.1244x; 1.1244x over previous
#include <cuda_runtime.h>
#include <cstdint>
#include <cstddef>

typedef unsigned int u32;
typedef unsigned long long u64;

// ---------------- problem dims ----------------
#define B_DIM 4096
#define I_DIM 256
#define H_DIM 1024
#define O_DIM 4096   // 4*H
#define MPL   4      // bit planes

#define NW_IH (MPL * I_DIM * O_DIM)   // 4,194,304
#define NW_HH (MPL * H_DIM * O_DIM)   // 16,777,216
#define N_B   (MPL * O_DIM)           // 16,384
#define N_NIB_IN (B_DIM * I_DIM)
#define N_NIB_HX (B_DIM * H_DIM)

// ---------------- static device scratch (no allocations allowed) ----------------
// Weff stored plane-interleaved: [K][O][MPL]
__device__ float   g_weff_ih[(size_t)I_DIM * O_DIM * MPL];      // 16 MB
__device__ float   g_weff_hh[(size_t)H_DIM * O_DIM * MPL];      // 64 MB
__device__ float   g_bq_ih[N_B];
__device__ float   g_nb_ih[N_B];
__device__ float   g_bq_hh[N_B];
__device__ float   g_nb_hh[N_B];
__device__ uint8_t g_nib_in[(size_t)N_NIB_IN];                  // 1 MB
__device__ uint8_t g_nib_hx[(size_t)N_NIB_HX];                  // 4 MB
__device__ float   g_gates1[(size_t)B_DIM * O_DIM];             // 64 MB (part1, ih)
__device__ float   g_gates2[(size_t)B_DIM * O_DIM];             // 64 MB (part2, hh)
__device__ unsigned g_max[4];
__device__ unsigned g_tile;                                      // persistent scheduler

// ---------------- threefry2x32 (JAX-exact) ----------------
__host__ __device__ __forceinline__ void threefry2x32(u32 k0, u32 k1, u32 x0, u32 x1,
                                                      u32 &o0, u32 &o1) {
  u32 ks2 = k0 ^ k1 ^ 0x1BD11BDAu;
  x0 += k0; x1 += k1;
#define TF_ROT(r) { x0 += x1; x1 = (x1 << (r)) | (x1 >> (32 - (r))); x1 ^= x0; }
  TF_ROT(13) TF_ROT(15) TF_ROT(26) TF_ROT(6)   x0 += k1;  x1 += ks2 + 1u;
  TF_ROT(17) TF_ROT(29) TF_ROT(16) TF_ROT(24)  x0 += ks2; x1 += k0 + 2u;
  TF_ROT(13) TF_ROT(15) TF_ROT(26) TF_ROT(6)   x0 += k0;  x1 += k1 + 3u;
  TF_ROT(17) TF_ROT(29) TF_ROT(16) TF_ROT(24)  x0 += k1;  x1 += ks2 + 4u;
  TF_ROT(13) TF_ROT(15) TF_ROT(26) TF_ROT(6)   x0 += ks2; x1 += k0 + 5u;
#undef TF_ROT
  o0 = x0; o1 = x1;
}

// ---------------- XLA-exact f32 transcendentals (unfused rn mul/add) --------
__device__ __forceinline__ float xla_log1p(float x) {
  float u = __fadd_rn(x, 1.0f);
  if (u == 1.0f) return x;
  return __fmul_rn(__fdiv_rn(x, __fsub_rn(u, 1.0f)), logf(u));
}

__device__ __forceinline__ float xla_erfinv(float x) {
  float w = -xla_log1p(__fmul_rn(__fmul_rn(-1.0f, x), x));
  float p;
  if (w < 5.0f) {
    w = __fsub_rn(w, 2.5f);
    p = 2.81022636e-08f;
    p = __fadd_rn(__fmul_rn(p, w), 3.43273939e-07f);
    p = __fadd_rn(__fmul_rn(p, w), -3.5233877e-06f);
    p = __fadd_rn(__fmul_rn(p, w), -4.39150654e-06f);
    p = __fadd_rn(__fmul_rn(p, w), 0.00021858087f);
    p = __fadd_rn(__fmul_rn(p, w), -0.00125372503f);
    p = __fadd_rn(__fmul_rn(p, w), -0.00417768164f);
    p = __fadd_rn(__fmul_rn(p, w), 0.246640727f);
    p = __fadd_rn(__fmul_rn(p, w), 1.50140941f);
  } else {
    w = __fsub_rn(sqrtf(w), 3.0f);
    p = -0.000200214257f;
    p = __fadd_rn(__fmul_rn(p, w), 0.000100950558f);
    p = __fadd_rn(__fmul_rn(p, w), 0.00134934322f);
    p = __fadd_rn(__fmul_rn(p, w), -0.00367342844f);
    p = __fadd_rn(__fmul_rn(p, w), 0.00573950773f);
    p = __fadd_rn(__fmul_rn(p, w), -0.0076224613f);
    p = __fadd_rn(__fmul_rn(p, w), 0.00943887047f);
    p = __fadd_rn(__fmul_rn(p, w), 1.00167406f);
    p = __fadd_rn(__fmul_rn(p, w), 2.83297682f);
  }
  return __fmul_rn(p, x);
}

__device__ __forceinline__ float xla_tanh(float x) {
  float ax = fabsf(x);
  if (ax < 0.0004f) return x;
  float xc = fminf(fmaxf(x, -7.90531110763549805f), 7.90531110763549805f);
  float x2 = __fmul_rn(xc, xc);
  float p = -2.76076847742355e-16f;
  p = __fadd_rn(__fmul_rn(p, x2), 2.00018790482477e-13f);
  p = __fadd_rn(__fmul_rn(p, x2), -8.60467152213735e-11f);
  p = __fadd_rn(__fmul_rn(p, x2), 5.12229709037114e-08f);
  p = __fadd_rn(__fmul_rn(p, x2), 1.48572235717979e-05f);
  p = __fadd_rn(__fmul_rn(p, x2), 6.37261928875436e-04f);
  p = __fadd_rn(__fmul_rn(p, x2), 4.89352455891786e-03f);
  p = __fmul_rn(p, xc);
  float q = 1.19825839466702e-06f;
  q = __fadd_rn(__fmul_rn(q, x2), 1.18534705686654e-04f);
  q = __fadd_rn(__fmul_rn(q, x2), 2.26843463243900e-03f);
  q = __fadd_rn(__fmul_rn(q, x2), 4.89352518554385e-03f);
  return __fdiv_rn(p, q);
}

__device__ __forceinline__ float xla_logistic(float x) {
  return __fadd_rn(0.5f, __fmul_rn(0.5f, xla_tanh(__fmul_rn(0.5f, x))));
}

// bits -> N(0,1) exactly as jax.random.normal (float32 path)
__device__ __forceinline__ float bits_to_normal(u32 bits) {
  float u = __uint_as_float((bits >> 9) | 0x3F800000u) - 1.0f;   // [0,1)
  const float lo = __uint_as_float(0xBF7FFFFFu);                 // nextafter(-1,0)
  float v = __fadd_rn(__fmul_rn(u, 2.0f), lo);
  v = fmaxf(v, lo);
  return __fmul_rn(__uint_as_float(0x3FB504F3u) /*sqrt2*/, xla_erfinv(v));
}

// partitionable threefry random_bits: bits[j] = o0 ^ o1 of TF(key, 0, j)
__device__ __forceinline__ u32 jax_bits32(u32 k0, u32 k1, u32 j) {
  u32 o0, o1; threefry2x32(k0, k1, 0u, j, o0, o1);
  return o0 ^ o1;
}

// ---------------- float max encoding for atomicMax ----------------
__device__ __forceinline__ unsigned fenc(float f) {
  unsigned u = __float_as_uint(f);
  return (u & 0x80000000u) ? ~u : (u | 0x80000000u);
}
__device__ __forceinline__ float fdec(unsigned u) {
  return (u & 0x80000000u) ? __uint_as_float(u & 0x7FFFFFFFu) : __uint_as_float(~u);
}

__global__ void k_init_max() {
  if (threadIdx.x < 4) g_max[threadIdx.x] = fenc(-__int_as_float(0x7F800000));
  if (threadIdx.x == 0) g_tile = 0u;
}

// one launch, 4 reductions (y selects the array)
__global__ void k_max4(const float* __restrict__ wih, const float* __restrict__ whh,
                       const float* __restrict__ bih, const float* __restrict__ bhh) {
  int slot = blockIdx.y;
  const float* x = (slot == 0) ? wih : (slot == 1) ? whh : (slot == 2) ? bih : bhh;
  int n = (slot == 0) ? NW_IH : (slot == 1) ? NW_HH : N_B;
  float m = -__int_as_float(0x7F800000);
  for (int i = blockIdx.x * blockDim.x + threadIdx.x; i < n; i += gridDim.x * blockDim.x)
    m = fmaxf(m, x[i]);
#pragma unroll
  for (int o = 16; o; o >>= 1) m = fmaxf(m, __shfl_xor_sync(0xFFFFFFFFu, m, o));
  if ((threadIdx.x & 31) == 0) atomicMax(&g_max[slot], fenc(m));
}

// quant(x, 8, 1.0) for weights
__device__ __forceinline__ float quant_w(float x) {
  float xs = fminf(fmaxf(x, -0.9921875f), 0.9921875f);
  return __fmul_rn(__fdiv_rn(rintf(__fmul_rn(xs, 128.0f)), 128.0f), 1.0f);
}

// Weff[k][o][m] = quant(W[m][k][o]) + normal(ctr = src linear)*wmax*0.1
// Both matrices in one launch: j < NW_IH -> ih, else hh.
__global__ void k_build_w_all(const float* __restrict__ Wih, const float* __restrict__ Whh,
                              u32 ka0, u32 ka1, u32 kb0, u32 kb1) {
  int j = blockIdx.x * blockDim.x + threadIdx.x;
  const float* W; float* dst; int K; u32 kk0, kk1; float wmax; int jj;
  if (j < NW_IH) {
    W = Wih; dst = g_weff_ih; K = I_DIM; kk0 = ka0; kk1 = ka1;
    wmax = fdec(g_max[0]); jj = j;
  } else {
    jj = j - NW_IH;
    if (jj >= NW_HH) return;
    W = Whh; dst = g_weff_hh; K = H_DIM; kk0 = kb0; kk1 = kb1;
    wmax = fdec(g_max[1]);
  }
  int k = jj >> 14;                 // O_DIM*MPL = 16384
  int rem = jj & 16383;
  int o = rem >> 2, m = rem & 3;
  u32 src = (u32)((m * K + k) * O_DIM + o);        // source linear = PRNG counter
  float nr = bits_to_normal(jax_bits32(kk0, kk1, src));
  dst[jj] = __fadd_rn(quant_w(W[src]), __fmul_rn(__fmul_rn(nr, wmax), 0.1f));
}

// biases (both): bq and nb separate so (mm + bq) + nb add order matches reference
__global__ void k_build_b_all(const float* __restrict__ Bih, const float* __restrict__ Bhh,
                              u32 ka0, u32 ka1, u32 kb0, u32 kb1) {
  int j = blockIdx.x * blockDim.x + threadIdx.x;
  if (j < N_B) {
    float bmax = fdec(g_max[2]);
    g_bq_ih[j] = quant_w(Bih[j]);
    g_nb_ih[j] = __fmul_rn(__fmul_rn(bits_to_normal(jax_bits32(ka0, ka1, (u32)j)), bmax), 0.1f);
  } else {
    int jj = j - N_B;
    if (jj >= N_B) return;
    float bmax = fdec(g_max[3]);
    g_bq_hh[jj] = quant_w(Bhh[jj]);
    g_nb_hh[jj] = __fmul_rn(__fmul_rn(bits_to_normal(jax_bits32(kb0, kb1, (u32)jj)), bmax), 0.1f);
  }
}

// activation -> 4-bit plane nibble (input branch then hx branch, one launch)
__global__ void k_nib_all(const float* __restrict__ input, const float* __restrict__ hx,
                          const float* __restrict__ a1P, const float* __restrict__ a11P) {
  int i = blockIdx.x * blockDim.x + threadIdx.x;
  float x, a, off; uint8_t* dst; int idx;
  float a1 = *a1P;
  if (i < N_NIB_IN) {
    x = input[i]; a = a1; off = a1; dst = g_nib_in; idx = i;
  } else {
    idx = i - N_NIB_IN;
    if (idx >= N_NIB_HX) return;
    x = hx[idx]; a = *a11P; off = a1; dst = g_nib_hx;   // '+ a1' quirk preserved
  }
  float t = __fdiv_rn(__fadd_rn(fminf(fmaxf(x, -a), a), off), __fmul_rn(a, 2.0f));
  float v = rintf(__fmul_rn(15.0f, t));
  dst[idx] = (uint8_t)(((int)v) & 15);
}

// ---------------- persistent GEMM (both branches, double-buffered smem) ------
// fma.rn.f32x2 lanes = plane pairs; per-lane acc = rn(w*mask + acc), mask in
// {0,1} via 16-entry LUT -> bit-identical to sequential ascending-k fp32 chain.
#define BM 64
#define BN 64
#define KC 32
#define N_TILES_HH 4096
#define N_TILES_ALL 8192
#define GRID_GEMM 304

#define SWB (KC * BN * MPL * 4)     // 32768 bytes per W buffer
#define SAB (BM * 8 * 4)            // 2048 bytes per A buffer
#define DSMEM_SZ (2 * SWB + 2 * SAB)  // 69632

__device__ __forceinline__ void fma2(u64 &acc, u64 w, u64 m) {
  asm volatile("fma.rn.f32x2 %0, %1, %2, %0;" : "+l"(acc) : "l"(w), "l"(m));
}
__device__ __forceinline__ void lds_v2u64(u64 &a, u64 &b, u32 addr) {
  asm volatile("ld.shared.v2.b64 {%0,%1}, [%2];" : "=l"(a), "=l"(b) : "r"(addr));
}
__device__ __forceinline__ void unpack2(u64 v, float &lo, float &hi) {
  u32 l, h;
  asm volatile("mov.b64 {%0,%1}, %2;" : "=r"(l), "=r"(h) : "l"(v));
  lo = __uint_as_float(l); hi = __uint_as_float(h);
}

__launch_bounds__(256, 2)
__global__ void k_gemm_all(const float* __restrict__ a1P, const float* __restrict__ a11P) {
  extern __shared__ __align__(16) char dsm[];
  // layout: W0 | W1 | A0 | A1
  __shared__ __align__(16) float4 sLut[16];
  __shared__ u32 sTile;

  int tid = threadIdx.x;
  if (tid < 16)
    sLut[tid] = make_float4((float)((tid >> 3) & 1), (float)((tid >> 2) & 1),
                            (float)((tid >> 1) & 1), (float)(tid & 1));
  int tx = tid & 15, ty = tid >> 4;
  int rowBase = ty * 4;

  u32 dsb = (u32)__cvta_generic_to_shared(dsm);
  u32 sLb = (u32)__cvta_generic_to_shared(sLut);
  u32 wbuf[2] = {dsb, dsb + SWB};
  u32 abuf[2] = {dsb + 2 * SWB, dsb + 2 * SWB + SAB};

  // staging register buffers
  float4 wld[8];
  u32 ald[2];

  while (true) {
    if (tid == 0) sTile = atomicAdd(&g_tile, 1u);
    __syncthreads();                 // orders sLut init / prev-tile smem reuse
    u32 t = sTile;
    if (t >= N_TILES_ALL) break;

    // hh tiles first (big), then ih (small) for a short ragged tail
    bool hh = (t < N_TILES_HH);
    u32 t2 = hh ? t : (t - N_TILES_HH);
    int K = hh ? H_DIM : I_DIM;
    const float* __restrict__ Wg = hh ? g_weff_hh : g_weff_ih;   // [K][O][MPL]
    const float* __restrict__ bq = hh ? g_bq_hh : g_bq_ih;
    const float* __restrict__ nb = hh ? g_nb_hh : g_nb_ih;
    const uint8_t* __restrict__ nibp = hh ? g_nib_hx : g_nib_in;
    float* __restrict__ gout = hh ? g_gates2 : g_gates1;
    float a = hh ? *a11P : *a1P;

    int ob = (int)(t2 & 63) * BN;
    int bb = (int)(t2 >> 6) * BM;

    // per-thread staging indices (fixed): A: idx=tid+t*256 -> r,k4 ; W: k,w4
    int ar0 = tid >> 3, ak0 = tid & 7;
    int ar1 = (tid + 256) >> 3, ak1 = (tid + 256) & 7;

    u64 acc[4][4][2];   // [row][col][plane-pair]
#pragma unroll
    for (int r = 0; r < 4; ++r)
#pragma unroll
      for (int c = 0; c < 4; ++c) { acc[r][c][0] = 0ull; acc[r][c][1] = 0ull; }

    int nk0 = K >> 5;   // K / KC

    // prefetch k0=0 into regs, store to buffer 0
    {
      ald[0] = *(const u32*)(nibp + (size_t)(bb + ar0) * K + ak0 * 4);
      ald[1] = *(const u32*)(nibp + (size_t)(bb + ar1) * K + ak1 * 4);
#pragma unroll
      for (int tt = 0; tt < 8; ++tt) {
        int idx = tid + tt * 256;
        int k = idx >> 6, w4 = idx & 63;
        wld[tt] = *(const float4*)(Wg + ((size_t)k * O_DIM + ob) * MPL + w4 * 4);
      }
      *(u32*)(dsm + 2 * SWB + (ar0 * 8 + ak0) * 4) = ald[0];
      *(u32*)(dsm + 2 * SWB + (ar1 * 8 + ak1) * 4) = ald[1];
#pragma unroll
      for (int tt = 0; tt < 8; ++tt) {
        int idx = tid + tt * 256;
        *(float4*)(dsm + idx * 16) = wld[tt];
      }
    }
    __syncthreads();

    for (int i0 = 0; i0 < nk0; ++i0) {
      int cur = i0 & 1;
      // issue next-stage loads early (latency overlapped with compute)
      if (i0 + 1 < nk0) {
        int k0n = (i0 + 1) << 5;
        ald[0] = *(const u32*)(nibp + (size_t)(bb + ar0) * K + k0n + ak0 * 4);
        ald[1] = *(const u32*)(nibp + (size_t)(bb + ar1) * K + k0n + ak1 * 4);
#pragma unroll
        for (int tt = 0; tt < 8; ++tt) {
          int idx = tid + tt * 256;
          int k = idx >> 6, w4 = idx & 63;
          wld[tt] = *(const float4*)(Wg + ((size_t)(k0n + k) * O_DIM + ob) * MPL + w4 * 4);
        }
      }

      // compute current buffer (identical arithmetic to round 6)
      u32 sWb = wbuf[cur];
      u32 sAb = abuf[cur];
#pragma unroll
      for (int k4 = 0; k4 < KC / 4; ++k4) {
        u32 av[4];
#pragma unroll
        for (int r = 0; r < 4; ++r)
          asm volatile("ld.shared.b32 %0, [%1];" : "=r"(av[r])
                       : "r"(sAb + (u32)(((rowBase + r) * 8 + k4) * 4)));
#pragma unroll
        for (int s = 0; s < 4; ++s) {
          int k = k4 * 4 + s;
          u64 mk[4][2];
#pragma unroll
          for (int r = 0; r < 4; ++r) {
            u32 ad = sLb + (((av[r] >> (8 * s)) & 15u) << 4);
            lds_v2u64(mk[r][0], mk[r][1], ad);
          }
#pragma unroll
          for (int c = 0; c < 4; ++c) {
            u64 w0, w1;
            u32 wad = sWb + (u32)(k * (BN * MPL * 4)) + (u32)((tx + 16 * c) * 16);
            lds_v2u64(w0, w1, wad);
#pragma unroll
            for (int r = 0; r < 4; ++r) {
              fma2(acc[r][c][0], w0, mk[r][0]);
              fma2(acc[r][c][1], w1, mk[r][1]);
            }
          }
        }
      }

      // publish next buffer
      if (i0 + 1 < nk0) {
        int nxt = cur ^ 1;
        char* wdst = dsm + nxt * SWB;
        char* adst = dsm + 2 * SWB + nxt * SAB;
        *(u32*)(adst + (ar0 * 8 + ak0) * 4) = ald[0];
        *(u32*)(adst + (ar1 * 8 + ak1) * 4) = ald[1];
#pragma unroll
        for (int tt = 0; tt < 8; ++tt) {
          int idx = tid + tt * 256;
          *(float4*)(wdst + idx * 16) = wld[tt];
        }
      }
      __syncthreads();
    }

    // epilogue: threshold per plane, beta-recombine, scale -> its own buffer
    float twoa = __fmul_rn(a, 2.0f);
    const float beta[MPL] = {8.0f / 15.0f, 4.0f / 15.0f, 2.0f / 15.0f, 1.0f / 15.0f};
#pragma unroll
    for (int r = 0; r < 4; ++r) {
#pragma unroll
      for (int c = 0; c < 4; ++c) {
        int b = bb + rowBase + r, o = ob + tx + 16 * c;
        float sv[4];
        unpack2(acc[r][c][0], sv[0], sv[1]);
        unpack2(acc[r][c][1], sv[2], sv[3]);
        float p = 0.0f;
#pragma unroll
        for (int m = 0; m < MPL; ++m) {
          float s = __fadd_rn(__fadd_rn(sv[m], bq[m * O_DIM + o]), nb[m * O_DIM + o]);
          p = __fadd_rn(p, (s > 0.5f) ? beta[m] : 0.0f);
        }
        gout[(size_t)b * O_DIM + o] = __fsub_rn(__fmul_rn(p, twoa), a);
      }
    }
  }
}

// ---------------- quantized LSTM pointwise tail ----------------
__device__ __forceinline__ float pactf(float x, float a) { return fminf(fmaxf(x, -a), a); }
__device__ __forceinline__ float quant8(float x, float r) {
  float xs = __fdiv_rn(x, r);
  xs = fminf(fmaxf(xs, -0.9921875f), 0.9921875f);
  return __fmul_rn(__fdiv_rn(rintf(__fmul_rn(xs, 128.0f)), 128.0f), r);
}

__global__ void k_lstm(const float* __restrict__ cx, float* __restrict__ out,
                       const float* a3, const float* a4, const float* a5, const float* a6,
                       const float* a7, const float* a8, const float* a9, const float* a10,
                       const float* a11) {
  int idx = blockIdx.x * blockDim.x + threadIdx.x;
  if (idx >= B_DIM * H_DIM) return;
  int b = idx >> 10, h = idx & (H_DIM - 1);
  const float* g1 = g_gates1 + (size_t)b * O_DIM;
  const float* g2 = g_gates2 + (size_t)b * O_DIM;
  float gi = __fadd_rn(g1[h],        g2[h]);
  float gj = __fadd_rn(g1[h + 1024], g2[h + 1024]);
  float gf = __fadd_rn(g1[h + 2048], g2[h + 2048]);
  float go = __fadd_rn(g1[h + 3072], g2[h + 3072]);

  float v3 = *a3, v4 = *a4, v5 = *a5, v6 = *a6, v7 = *a7, v8 = *a8, v9 = *a9,
        v10 = *a10, v11 = *a11;
  float fg  = quant8(pactf(xla_logistic(gf), v3), v3);
  float ig  = quant8(pactf(xla_logistic(gi), v4), v4);
  float act = quant8(pactf(xla_tanh(gj), v5), v5);
  float og  = quant8(pactf(xla_logistic(go), v6), v6);
  float gated = quant8(pactf(__fmul_rn(cx[idx], fg), v7), v7);
  float actin = quant8(pactf(__fmul_rn(ig, act), v8), v8);
  float newc  = quant8(pactf(__fadd_rn(gated, actin), v9), v9);
  float actc  = quant8(pactf(xla_tanh(newc), v10), v10);
  float newh  = quant8(pactf(__fmul_rn(actc, og), v11), v11);
  out[idx] = newh;
  out[(size_t)B_DIM * H_DIM + idx] = newc;
}

// ---------------- host side ----------------
static void split2(const u32 k[2], u32 ka[2], u32 kb[2]) {
  threefry2x32(k[0], k[1], 0u, 0u, ka[0], ka[1]);
  threefry2x32(k[0], k[1], 0u, 1u, kb[0], kb[1]);
}

extern "C" void kernel_launch(void* const* d_in, const int* in_sizes, int n_in,
                              void* d_out, int out_size) {
  const float* input = (const float*)d_in[0];
  const float* hx    = (const float*)d_in[1];
  const float* cx    = (const float*)d_in[2];
  const float* wih   = (const float*)d_in[3];
  const float* whh   = (const float*)d_in[4];
  const float* bih   = (const float*)d_in[5];
  const float* bhh   = (const float*)d_in[6];
  const float* a1  = (const float*)d_in[7];
  const float* a3  = (const float*)d_in[8];
  const float* a4  = (const float*)d_in[9];
  const float* a5  = (const float*)d_in[10];
  const float* a6  = (const float*)d_in[11];
  const float* a7  = (const float*)d_in[12];
  const float* a8  = (const float*)d_in[13];
  const float* a9  = (const float*)d_in[14];
  const float* a10 = (const float*)d_in[15];
  const float* a11 = (const float*)d_in[16];

  u32 root[2] = {0u, 42u}, K1[2], K2[2], KW1[2], KB1[2], KW2[2], KB2[2];
  split2(root, K1, K2);
  split2(K1, KW1, KB1);
  split2(K2, KW2, KB2);

  static bool attr_done = false;
  if (!attr_done) {
    cudaFuncSetAttribute(k_gemm_all, cudaFuncAttributeMaxDynamicSharedMemorySize, DSMEM_SZ);
    attr_done = true;
  }

  k_init_max<<<1, 32>>>();
  {
    dim3 g(512, 4);
    k_max4<<<g, 256>>>(wih, whh, bih, bhh);
  }

  k_build_w_all<<<(NW_IH + NW_HH + 255) / 256, 256>>>(wih, whh,
                                                      KW1[0], KW1[1], KW2[0], KW2[1]);
  k_build_b_all<<<(2 * N_B + 255) / 256, 256>>>(bih, bhh,
                                                KB1[0], KB1[1], KB2[0], KB2[1]);
  k_nib_all<<<(N_NIB_IN + N_NIB_HX + 255) / 256, 256>>>(input, hx, a1, a11);

  // one persistent kernel: hh tiles (0..4095) then ih tiles (4096..8191)
  k_gemm_all<<<GRID_GEMM, 256, DSMEM_SZ>>>(a1, a11);

  k_lstm<<<(B_DIM * H_DIM + 255) / 256, 256>>>(cx, (float*)d_out,
                                               a3, a4, a5, a6, a7, a8, a9, a10, a11);
}

// round 9
// speedup vs baseline: 1.2489x; 1.1107x over previous
#include <cuda_runtime.h>
#include <cstdint>
#include <cstddef>

typedef unsigned int u32;
typedef unsigned long long u64;

// ---------------- problem dims ----------------
#define B_DIM 4096
#define I_DIM 256
#define H_DIM 1024
#define O_DIM 4096   // 4*H
#define MPL   4      // bit planes

#define NW_IH (MPL * I_DIM * O_DIM)   // 4,194,304
#define NW_HH (MPL * H_DIM * O_DIM)   // 16,777,216
#define N_B   (MPL * O_DIM)           // 16,384
#define N_NIB_IN (B_DIM * I_DIM)
#define N_NIB_HX (B_DIM * H_DIM)

// ---------------- static device scratch (no allocations allowed) ----------------
// Weff stored plane-interleaved: [K][O][MPL]
__device__ float   g_weff_ih[(size_t)I_DIM * O_DIM * MPL];      // 16 MB
__device__ float   g_weff_hh[(size_t)H_DIM * O_DIM * MPL];      // 64 MB
__device__ float   g_bq_ih[N_B];
__device__ float   g_nb_ih[N_B];
__device__ float   g_bq_hh[N_B];
__device__ float   g_nb_hh[N_B];
__device__ uint8_t g_nib_in[(size_t)N_NIB_IN];                  // 1 MB
__device__ uint8_t g_nib_hx[(size_t)N_NIB_HX];                  // 4 MB
__device__ float   g_gates1[(size_t)B_DIM * O_DIM];             // 64 MB (part1, ih)
__device__ float   g_gates2[(size_t)B_DIM * O_DIM];             // 64 MB (part2, hh)
__device__ unsigned g_max[4];
__device__ unsigned g_tile;                                      // persistent scheduler

// ---------------- threefry2x32 (JAX-exact) ----------------
__host__ __device__ __forceinline__ void threefry2x32(u32 k0, u32 k1, u32 x0, u32 x1,
                                                      u32 &o0, u32 &o1) {
  u32 ks2 = k0 ^ k1 ^ 0x1BD11BDAu;
  x0 += k0; x1 += k1;
#define TF_ROT(r) { x0 += x1; x1 = (x1 << (r)) | (x1 >> (32 - (r))); x1 ^= x0; }
  TF_ROT(13) TF_ROT(15) TF_ROT(26) TF_ROT(6)   x0 += k1;  x1 += ks2 + 1u;
  TF_ROT(17) TF_ROT(29) TF_ROT(16) TF_ROT(24)  x0 += ks2; x1 += k0 + 2u;
  TF_ROT(13) TF_ROT(15) TF_ROT(26) TF_ROT(6)   x0 += k0;  x1 += k1 + 3u;
  TF_ROT(17) TF_ROT(29) TF_ROT(16) TF_ROT(24)  x0 += k1;  x1 += ks2 + 4u;
  TF_ROT(13) TF_ROT(15) TF_ROT(26) TF_ROT(6)   x0 += ks2; x1 += k0 + 5u;
#undef TF_ROT
  o0 = x0; o1 = x1;
}

// ---------------- XLA-exact f32 transcendentals (unfused rn mul/add) --------
__device__ __forceinline__ float xla_log1p(float x) {
  float u = __fadd_rn(x, 1.0f);
  if (u == 1.0f) return x;
  return __fmul_rn(__fdiv_rn(x, __fsub_rn(u, 1.0f)), logf(u));
}

__device__ __forceinline__ float xla_erfinv(float x) {
  float w = -xla_log1p(__fmul_rn(__fmul_rn(-1.0f, x), x));
  float p;
  if (w < 5.0f) {
    w = __fsub_rn(w, 2.5f);
    p = 2.81022636e-08f;
    p = __fadd_rn(__fmul_rn(p, w), 3.43273939e-07f);
    p = __fadd_rn(__fmul_rn(p, w), -3.5233877e-06f);
    p = __fadd_rn(__fmul_rn(p, w), -4.39150654e-06f);
    p = __fadd_rn(__fmul_rn(p, w), 0.00021858087f);
    p = __fadd_rn(__fmul_rn(p, w), -0.00125372503f);
    p = __fadd_rn(__fmul_rn(p, w), -0.00417768164f);
    p = __fadd_rn(__fmul_rn(p, w), 0.246640727f);
    p = __fadd_rn(__fmul_rn(p, w), 1.50140941f);
  } else {
    w = __fsub_rn(sqrtf(w), 3.0f);
    p = -0.000200214257f;
    p = __fadd_rn(__fmul_rn(p, w), 0.000100950558f);
    p = __fadd_rn(__fmul_rn(p, w), 0.00134934322f);
    p = __fadd_rn(__fmul_rn(p, w), -0.00367342844f);
    p = __fadd_rn(__fmul_rn(p, w), 0.00573950773f);
    p = __fadd_rn(__fmul_rn(p, w), -0.0076224613f);
    p = __fadd_rn(__fmul_rn(p, w), 0.00943887047f);
    p = __fadd_rn(__fmul_rn(p, w), 1.00167406f);
    p = __fadd_rn(__fmul_rn(p, w), 2.83297682f);
  }
  return __fmul_rn(p, x);
}

__device__ __forceinline__ float xla_tanh(float x) {
  float ax = fabsf(x);
  if (ax < 0.0004f) return x;
  float xc = fminf(fmaxf(x, -7.90531110763549805f), 7.90531110763549805f);
  float x2 = __fmul_rn(xc, xc);
  float p = -2.76076847742355e-16f;
  p = __fadd_rn(__fmul_rn(p, x2), 2.00018790482477e-13f);
  p = __fadd_rn(__fmul_rn(p, x2), -8.60467152213735e-11f);
  p = __fadd_rn(__fmul_rn(p, x2), 5.12229709037114e-08f);
  p = __fadd_rn(__fmul_rn(p, x2), 1.48572235717979e-05f);
  p = __fadd_rn(__fmul_rn(p, x2), 6.37261928875436e-04f);
  p = __fadd_rn(__fmul_rn(p, x2), 4.89352455891786e-03f);
  p = __fmul_rn(p, xc);
  float q = 1.19825839466702e-06f;
  q = __fadd_rn(__fmul_rn(q, x2), 1.18534705686654e-04f);
  q = __fadd_rn(__fmul_rn(q, x2), 2.26843463243900e-03f);
  q = __fadd_rn(__fmul_rn(q, x2), 4.89352518554385e-03f);
  return __fdiv_rn(p, q);
}

__device__ __forceinline__ float xla_logistic(float x) {
  return __fadd_rn(0.5f, __fmul_rn(0.5f, xla_tanh(__fmul_rn(0.5f, x))));
}

// bits -> N(0,1) exactly as jax.random.normal (float32 path)
__device__ __forceinline__ float bits_to_normal(u32 bits) {
  float u = __uint_as_float((bits >> 9) | 0x3F800000u) - 1.0f;   // [0,1)
  const float lo = __uint_as_float(0xBF7FFFFFu);                 // nextafter(-1,0)
  float v = __fadd_rn(__fmul_rn(u, 2.0f), lo);
  v = fmaxf(v, lo);
  return __fmul_rn(__uint_as_float(0x3FB504F3u) /*sqrt2*/, xla_erfinv(v));
}

// partitionable threefry random_bits: bits[j] = o0 ^ o1 of TF(key, 0, j)
__device__ __forceinline__ u32 jax_bits32(u32 k0, u32 k1, u32 j) {
  u32 o0, o1; threefry2x32(k0, k1, 0u, j, o0, o1);
  return o0 ^ o1;
}

// ---------------- float max encoding for atomicMax ----------------
__device__ __forceinline__ unsigned fenc(float f) {
  unsigned u = __float_as_uint(f);
  return (u & 0x80000000u) ? ~u : (u | 0x80000000u);
}
__device__ __forceinline__ float fdec(unsigned u) {
  return (u & 0x80000000u) ? __uint_as_float(u & 0x7FFFFFFFu) : __uint_as_float(~u);
}

__global__ void k_init_max() {
  if (threadIdx.x < 4) g_max[threadIdx.x] = fenc(-__int_as_float(0x7F800000));
  if (threadIdx.x == 0) g_tile = 0u;
}

// one launch, 4 reductions (y selects the array)
__global__ void k_max4(const float* __restrict__ wih, const float* __restrict__ whh,
                       const float* __restrict__ bih, const float* __restrict__ bhh) {
  int slot = blockIdx.y;
  const float* x = (slot == 0) ? wih : (slot == 1) ? whh : (slot == 2) ? bih : bhh;
  int n = (slot == 0) ? NW_IH : (slot == 1) ? NW_HH : N_B;
  float m = -__int_as_float(0x7F800000);
  for (int i = blockIdx.x * blockDim.x + threadIdx.x; i < n; i += gridDim.x * blockDim.x)
    m = fmaxf(m, x[i]);
#pragma unroll
  for (int o = 16; o; o >>= 1) m = fmaxf(m, __shfl_xor_sync(0xFFFFFFFFu, m, o));
  if ((threadIdx.x & 31) == 0) atomicMax(&g_max[slot], fenc(m));
}

// quant(x, 8, 1.0) for weights
__device__ __forceinline__ float quant_w(float x) {
  float xs = fminf(fmaxf(x, -0.9921875f), 0.9921875f);
  return __fmul_rn(__fdiv_rn(rintf(__fmul_rn(xs, 128.0f)), 128.0f), 1.0f);
}

// Weff[k][o][m] = quant(W[m][k][o]) + normal(ctr = src linear)*wmax*0.1
// Both matrices in one launch: j < NW_IH -> ih, else hh.
__global__ void k_build_w_all(const float* __restrict__ Wih, const float* __restrict__ Whh,
                              u32 ka0, u32 ka1, u32 kb0, u32 kb1) {
  int j = blockIdx.x * blockDim.x + threadIdx.x;
  const float* W; float* dst; int K; u32 kk0, kk1; float wmax; int jj;
  if (j < NW_IH) {
    W = Wih; dst = g_weff_ih; K = I_DIM; kk0 = ka0; kk1 = ka1;
    wmax = fdec(g_max[0]); jj = j;
  } else {
    jj = j - NW_IH;
    if (jj >= NW_HH) return;
    W = Whh; dst = g_weff_hh; K = H_DIM; kk0 = kb0; kk1 = kb1;
    wmax = fdec(g_max[1]);
  }
  int k = jj >> 14;                 // O_DIM*MPL = 16384
  int rem = jj & 16383;
  int o = rem >> 2, m = rem & 3;
  u32 src = (u32)((m * K + k) * O_DIM + o);        // source linear = PRNG counter
  float nr = bits_to_normal(jax_bits32(kk0, kk1, src));
  dst[jj] = __fadd_rn(quant_w(W[src]), __fmul_rn(__fmul_rn(nr, wmax), 0.1f));
}

// biases (both): bq and nb separate so (mm + bq) + nb add order matches reference
__global__ void k_build_b_all(const float* __restrict__ Bih, const float* __restrict__ Bhh,
                              u32 ka0, u32 ka1, u32 kb0, u32 kb1) {
  int j = blockIdx.x * blockDim.x + threadIdx.x;
  if (j < N_B) {
    float bmax = fdec(g_max[2]);
    g_bq_ih[j] = quant_w(Bih[j]);
    g_nb_ih[j] = __fmul_rn(__fmul_rn(bits_to_normal(jax_bits32(ka0, ka1, (u32)j)), bmax), 0.1f);
  } else {
    int jj = j - N_B;
    if (jj >= N_B) return;
    float bmax = fdec(g_max[3]);
    g_bq_hh[jj] = quant_w(Bhh[jj]);
    g_nb_hh[jj] = __fmul_rn(__fmul_rn(bits_to_normal(jax_bits32(kb0, kb1, (u32)jj)), bmax), 0.1f);
  }
}

// activation -> 4-bit plane nibble (input branch then hx branch, one launch)
__global__ void k_nib_all(const float* __restrict__ input, const float* __restrict__ hx,
                          const float* __restrict__ a1P, const float* __restrict__ a11P) {
  int i = blockIdx.x * blockDim.x + threadIdx.x;
  float x, a, off; uint8_t* dst; int idx;
  float a1 = *a1P;
  if (i < N_NIB_IN) {
    x = input[i]; a = a1; off = a1; dst = g_nib_in; idx = i;
  } else {
    idx = i - N_NIB_IN;
    if (idx >= N_NIB_HX) return;
    x = hx[idx]; a = *a11P; off = a1; dst = g_nib_hx;   // '+ a1' quirk preserved
  }
  float t = __fdiv_rn(__fadd_rn(fminf(fmaxf(x, -a), a), off), __fmul_rn(a, 2.0f));
  float v = rintf(__fmul_rn(15.0f, t));
  dst[idx] = (uint8_t)(((int)v) & 15);
}

// ---------------- persistent GEMM (both branches, one kernel) ----------------
// fma.rn.f32x2 lanes = plane pairs; per-lane acc = rn(w*mask + acc), mask in
// {0,1} via 16-entry LUT -> bit-identical to sequential ascending-k fp32 chain.
// Inner loop byte-identical to the proven round-6 configuration.
#define BM 64
#define BN 64
#define KC 32
#define N_TILES_HH 4096
#define N_TILES_ALL 8192
#define GRID_GEMM 304               // GB300: 152 SMs x 2 blocks/SM

__device__ __forceinline__ void fma2(u64 &acc, u64 w, u64 m) {
  asm volatile("fma.rn.f32x2 %0, %1, %2, %0;" : "+l"(acc) : "l"(w), "l"(m));
}
__device__ __forceinline__ void lds_v2u64(u64 &a, u64 &b, u32 addr) {
  asm volatile("ld.shared.v2.b64 {%0,%1}, [%2];" : "=l"(a), "=l"(b) : "r"(addr));
}
__device__ __forceinline__ void unpack2(u64 v, float &lo, float &hi) {
  u32 l, h;
  asm volatile("mov.b64 {%0,%1}, %2;" : "=r"(l), "=r"(h) : "l"(v));
  lo = __uint_as_float(l); hi = __uint_as_float(h);
}

__launch_bounds__(256, 2)
__global__ void k_gemm_all(const float* __restrict__ a1P, const float* __restrict__ a11P) {
  __shared__ __align__(16) float sW[KC][BN * MPL];   // 32 KB, [k][o*4+m]
  __shared__ u32 sA[BM][KC / 4];                     // 2 KB
  __shared__ __align__(16) float4 sLut[16];
  __shared__ u32 sTile;

  int tid = threadIdx.x;
  if (tid < 16)
    sLut[tid] = make_float4((float)((tid >> 3) & 1), (float)((tid >> 2) & 1),
                            (float)((tid >> 1) & 1), (float)(tid & 1));
  int tx = tid & 15, ty = tid >> 4;
  int rowBase = ty * 4;

  u32 sWb = (u32)__cvta_generic_to_shared(sW);
  u32 sLb = (u32)__cvta_generic_to_shared(sLut);

  while (true) {
    if (tid == 0) sTile = atomicAdd(&g_tile, 1u);
    __syncthreads();                 // also orders sLut init / prev-tile smem reuse
    u32 t = sTile;
    if (t >= N_TILES_ALL) break;

    // hh tiles first (big), then ih (small) for a short ragged tail
    bool hh = (t < N_TILES_HH);
    u32 t2 = hh ? t : (t - N_TILES_HH);
    int K = hh ? H_DIM : I_DIM;
    const float* __restrict__ Wg = hh ? g_weff_hh : g_weff_ih;   // [K][O][MPL]
    const float* __restrict__ bq = hh ? g_bq_hh : g_bq_ih;
    const float* __restrict__ nb = hh ? g_nb_hh : g_nb_ih;
    const uint8_t* __restrict__ nibp = hh ? g_nib_hx : g_nib_in;
    float* __restrict__ gout = hh ? g_gates2 : g_gates1;
    float a = hh ? *a11P : *a1P;

    int ob = (int)(t2 & 63) * BN;
    int bb = (int)(t2 >> 6) * BM;

    u64 acc[4][4][2];   // [row][col][plane-pair]
#pragma unroll
    for (int r = 0; r < 4; ++r)
#pragma unroll
      for (int c = 0; c < 4; ++c) { acc[r][c][0] = 0ull; acc[r][c][1] = 0ull; }

    for (int k0 = 0; k0 < K; k0 += KC) {
#pragma unroll
      for (int tt = 0; tt < 2; ++tt) {            // A tile: 64 rows x 8 u32
        int idx = tid + tt * 256;
        int r = idx >> 3, k4 = idx & 7;
        sA[r][k4] = *(const u32*)(nibp + (size_t)(bb + r) * K + k0 + k4 * 4);
      }
#pragma unroll
      for (int tt = 0; tt < 8; ++tt) {            // W tile: 2048 contiguous float4
        int idx = tid + tt * 256;
        int k = idx >> 6, w4 = idx & 63;
        *(float4*)&sW[k][w4 * 4] =
            *(const float4*)(Wg + ((size_t)(k0 + k) * O_DIM + ob) * MPL + w4 * 4);
      }
      __syncthreads();

#pragma unroll
      for (int k4 = 0; k4 < KC / 4; ++k4) {
        u32 av[4];
#pragma unroll
        for (int r = 0; r < 4; ++r) av[r] = sA[rowBase + r][k4];
#pragma unroll
        for (int s = 0; s < 4; ++s) {
          int k = k4 * 4 + s;
          u64 mk[4][2];
#pragma unroll
          for (int r = 0; r < 4; ++r) {
            u32 ad = sLb + (((av[r] >> (8 * s)) & 15u) << 4);
            lds_v2u64(mk[r][0], mk[r][1], ad);
          }
#pragma unroll
          for (int c = 0; c < 4; ++c) {
            u64 w0, w1;
            u32 wad = sWb + (u32)(k * (BN * MPL * 4)) + (u32)((tx + 16 * c) * 16);
            lds_v2u64(w0, w1, wad);
#pragma unroll
            for (int r = 0; r < 4; ++r) {
              fma2(acc[r][c][0], w0, mk[r][0]);
              fma2(acc[r][c][1], w1, mk[r][1]);
            }
          }
        }
      }
      __syncthreads();
    }

    // epilogue: threshold per plane, beta-recombine, scale -> its own buffer
    float twoa = __fmul_rn(a, 2.0f);
    const float beta[MPL] = {8.0f / 15.0f, 4.0f / 15.0f, 2.0f / 15.0f, 1.0f / 15.0f};
#pragma unroll
    for (int r = 0; r < 4; ++r) {
#pragma unroll
      for (int c = 0; c < 4; ++c) {
        int b = bb + rowBase + r, o = ob + tx + 16 * c;
        float sv[4];
        unpack2(acc[r][c][0], sv[0], sv[1]);
        unpack2(acc[r][c][1], sv[2], sv[3]);
        float p = 0.0f;
#pragma unroll
        for (int m = 0; m < MPL; ++m) {
          float s = __fadd_rn(__fadd_rn(sv[m], bq[m * O_DIM + o]), nb[m * O_DIM + o]);
          p = __fadd_rn(p, (s > 0.5f) ? beta[m] : 0.0f);
        }
        gout[(size_t)b * O_DIM + o] = __fsub_rn(__fmul_rn(p, twoa), a);
      }
    }
  }
}

// ---------------- quantized LSTM pointwise tail ----------------
__device__ __forceinline__ float pactf(float x, float a) { return fminf(fmaxf(x, -a), a); }
__device__ __forceinline__ float quant8(float x, float r) {
  float xs = __fdiv_rn(x, r);
  xs = fminf(fmaxf(xs, -0.9921875f), 0.9921875f);
  return __fmul_rn(__fdiv_rn(rintf(__fmul_rn(xs, 128.0f)), 128.0f), r);
}

__global__ void k_lstm(const float* __restrict__ cx, float* __restrict__ out,
                       const float* a3, const float* a4, const float* a5, const float* a6,
                       const float* a7, const float* a8, const float* a9, const float* a10,
                       const float* a11) {
  int idx = blockIdx.x * blockDim.x + threadIdx.x;
  if (idx >= B_DIM * H_DIM) return;
  int b = idx >> 10, h = idx & (H_DIM - 1);
  const float* g1 = g_gates1 + (size_t)b * O_DIM;
  const float* g2 = g_gates2 + (size_t)b * O_DIM;
  float gi = __fadd_rn(g1[h],        g2[h]);
  float gj = __fadd_rn(g1[h + 1024], g2[h + 1024]);
  float gf = __fadd_rn(g1[h + 2048], g2[h + 2048]);
  float go = __fadd_rn(g1[h + 3072], g2[h + 3072]);

  float v3 = *a3, v4 = *a4, v5 = *a5, v6 = *a6, v7 = *a7, v8 = *a8, v9 = *a9,
        v10 = *a10, v11 = *a11;
  float fg  = quant8(pactf(xla_logistic(gf), v3), v3);
  float ig  = quant8(pactf(xla_logistic(gi), v4), v4);
  float act = quant8(pactf(xla_tanh(gj), v5), v5);
  float og  = quant8(pactf(xla_logistic(go), v6), v6);
  float gated = quant8(pactf(__fmul_rn(cx[idx], fg), v7), v7);
  float actin = quant8(pactf(__fmul_rn(ig, act), v8), v8);
  float newc  = quant8(pactf(__fadd_rn(gated, actin), v9), v9);
  float actc  = quant8(pactf(xla_tanh(newc), v10), v10);
  float newh  = quant8(pactf(__fmul_rn(actc, og), v11), v11);
  out[idx] = newh;
  out[(size_t)B_DIM * H_DIM + idx] = newc;
}

// ---------------- host side ----------------
static void split2(const u32 k[2], u32 ka[2], u32 kb[2]) {
  threefry2x32(k[0], k[1], 0u, 0u, ka[0], ka[1]);
  threefry2x32(k[0], k[1], 0u, 1u, kb[0], kb[1]);
}

extern "C" void kernel_launch(void* const* d_in, const int* in_sizes, int n_in,
                              void* d_out, int out_size) {
  const float* input = (const float*)d_in[0];
  const float* hx    = (const float*)d_in[1];
  const float* cx    = (const float*)d_in[2];
  const float* wih   = (const float*)d_in[3];
  const float* whh   = (const float*)d_in[4];
  const float* bih   = (const float*)d_in[5];
  const float* bhh   = (const float*)d_in[6];
  const float* a1  = (const float*)d_in[7];
  const float* a3  = (const float*)d_in[8];
  const float* a4  = (const float*)d_in[9];
  const float* a5  = (const float*)d_in[10];
  const float* a6  = (const float*)d_in[11];
  const float* a7  = (const float*)d_in[12];
  const float* a8  = (const float*)d_in[13];
  const float* a9  = (const float*)d_in[14];
  const float* a10 = (const float*)d_in[15];
  const float* a11 = (const float*)d_in[16];

  u32 root[2] = {0u, 42u}, K1[2], K2[2], KW1[2], KB1[2], KW2[2], KB2[2];
  split2(root, K1, K2);
  split2(K1, KW1, KB1);
  split2(K2, KW2, KB2);

  k_init_max<<<1, 32>>>();
  {
    dim3 g(512, 4);
    k_max4<<<g, 256>>>(wih, whh, bih, bhh);
  }

  k_build_w_all<<<(NW_IH + NW_HH + 255) / 256, 256>>>(wih, whh,
                                                      KW1[0], KW1[1], KW2[0], KW2[1]);
  k_build_b_all<<<(2 * N_B + 255) / 256, 256>>>(bih, bhh,
                                                KB1[0], KB1[1], KB2[0], KB2[1]);
  k_nib_all<<<(N_NIB_IN + N_NIB_HX + 255) / 256, 256>>>(input, hx, a1, a11);

  // one persistent kernel: hh tiles (0..4095) then ih tiles (4096..8191)
  k_gemm_all<<<GRID_GEMM, 256>>>(a1, a11);

  k_lstm<<<(B_DIM * H_DIM + 255) / 256, 256>>>(cx, (float*)d_out,
                                               a3, a4, a5, a6, a7, a8, a9, a10, a11);
}